// round 2
// baseline (speedup 1.0000x reference)
#include <cuda_runtime.h>
#include <cstdint>

#define N_STEPS 1000

// Per-step fwd keys [0..999] + reverse key [1000]: {k0, k1, k2, 0}
__device__ uint4 g_keys[N_STEPS + 1];

// pre-scale all erfinv coefficients by 0.1 * sqrt(2)
#define SC(c) (0.14142136f * (c))

// ---------------- packed f32x2 helpers ----------------
__device__ __forceinline__ uint64_t pkf(float a, float b) {
    uint64_t r; asm("mov.b64 %0, {%1, %2};" : "=l"(r) : "f"(a), "f"(b)); return r;
}
__device__ __forceinline__ uint64_t pku(uint32_t a, uint32_t b) {
    uint64_t r; asm("mov.b64 %0, {%1, %2};" : "=l"(r) : "r"(a), "r"(b)); return r;
}
__device__ __forceinline__ float2 unpk(uint64_t v) {
    float2 f; asm("mov.b64 {%0, %1}, %2;" : "=f"(f.x), "=f"(f.y) : "l"(v)); return f;
}
__device__ __forceinline__ uint64_t fma2_(uint64_t a, uint64_t b, uint64_t c) {
    uint64_t d; asm("fma.rn.f32x2 %0, %1, %2, %3;" : "=l"(d) : "l"(a), "l"(b), "l"(c)); return d;
}
__device__ __forceinline__ uint64_t add2_(uint64_t a, uint64_t b) {
    uint64_t d; asm("add.rn.f32x2 %0, %1, %2;" : "=l"(d) : "l"(a), "l"(b)); return d;
}

// ---------------- Threefry-2x32 rounds ----------------
// SHF-based round (alu pipe)
__device__ __forceinline__ void rs(uint32_t& x0, uint32_t& x1, int r) {
    x0 += x1;
    x1 = __funnelshift_l(x1, x1, r) ^ x0;
}
// rotl via mul.wide (IMAD.WIDE on fma pipe); (lo|hi)^x0 fuses to one LOP3
__device__ __forceinline__ uint32_t rotm(uint32_t x, uint32_t m) {
    uint32_t lo, hi;
    asm("{\n\t.reg .u64 t;\n\tmul.wide.u32 t, %2, %3;\n\tmov.b64 {%0, %1}, t;\n\t}"
        : "=r"(lo), "=r"(hi) : "r"(x), "r"(m));
    return lo | hi;
}
__device__ __forceinline__ void rm(uint32_t& x0, uint32_t& x1, uint32_t m) {
    uint32_t rr = rotm(x1, m);   // independent of the add below -> ILP
    x0 += x1;
    x1 = rr ^ x0;
}

// full 20-round block, returns o0 ^ o1 (partitionable random_bits semantics)
__device__ __forceinline__ uint32_t tf_xor(uint32_t k0, uint32_t k1, uint32_t k2, uint32_t c1,
                                           uint32_t m13, uint32_t m26, uint32_t m17, uint32_t m16) {
    uint32_t x1 = c1 + k1;
    uint32_t x0 = k0 + x1;               // round 1 add with x0-init folded (c0 = 0)
    x1 = rotm(x1, m13) ^ x0;             // round 1 rot/xor
    rs(x0, x1, 15); rm(x0, x1, m26); rs(x0, x1, 6);
    x1 += k2 + 1u; x0 += k1;
    rm(x0, x1, m17); rs(x0, x1, 29); rm(x0, x1, m16); rs(x0, x1, 24);
    x1 += k0 + 2u; x0 += k2;
    rm(x0, x1, m13); rs(x0, x1, 15); rm(x0, x1, m26); rs(x0, x1, 6);
    x1 += k1 + 3u; x0 += k0;
    rm(x0, x1, m17); rs(x0, x1, 29); rm(x0, x1, m16); rs(x0, x1, 24);
    x1 += k2 + 4u; x0 += k1;
    rm(x0, x1, m13); rs(x0, x1, 15); rm(x0, x1, m26); rs(x0, x1, 6);
    return (x0 + k2) ^ (x1 + k0 + 5u);
}

// scalar threefry for key prep (plain version, perf-irrelevant)
__device__ __forceinline__ void tf_round_s(uint32_t& x0, uint32_t& x1, int r) {
    x0 += x1; x1 = __funnelshift_l(x1, x1, r) ^ x0;
}
__device__ void threefry2x32(uint32_t k0, uint32_t k1, uint32_t c0, uint32_t c1,
                             uint32_t& o0, uint32_t& o1) {
    const uint32_t k2 = k0 ^ k1 ^ 0x1BD11BDAu;
    uint32_t x0 = c0 + k0, x1 = c1 + k1;
    tf_round_s(x0,x1,13); tf_round_s(x0,x1,15); tf_round_s(x0,x1,26); tf_round_s(x0,x1,6);
    x0 += k1; x1 += k2 + 1u;
    tf_round_s(x0,x1,17); tf_round_s(x0,x1,29); tf_round_s(x0,x1,16); tf_round_s(x0,x1,24);
    x0 += k2; x1 += k0 + 2u;
    tf_round_s(x0,x1,13); tf_round_s(x0,x1,15); tf_round_s(x0,x1,26); tf_round_s(x0,x1,6);
    x0 += k0; x1 += k1 + 3u;
    tf_round_s(x0,x1,17); tf_round_s(x0,x1,29); tf_round_s(x0,x1,16); tf_round_s(x0,x1,24);
    x0 += k1; x1 += k2 + 4u;
    tf_round_s(x0,x1,13); tf_round_s(x0,x1,15); tf_round_s(x0,x1,26); tf_round_s(x0,x1,6);
    o0 = x0 + k2; o1 = x1 + k0 + 5u;
}

__global__ void prep_keys_kernel() {
    int t = threadIdx.x;
    if (t > N_STEPS) return;
    uint32_t k1 = (t < N_STEPS) ? 1u : 2u;
    uint32_t c1 = (t < N_STEPS) ? (uint32_t)t : 999u;
    uint32_t o0, o1;
    threefry2x32(0u, k1, 0u, c1, o0, o1);
    g_keys[t] = make_uint4(o0, o1, o0 ^ o1 ^ 0x1BD11BDAu, 0u);
}

// tail branch of erfinv (w >= 5), coefficients pre-scaled; z = w - 2.5
__device__ __forceinline__ float tailp(float z) {
    float w = z + 2.5f;
    float zz = __fsqrt_rn(w) - 3.0f;
    float p = SC(-0.000200214257f);
    p = fmaf(p, zz, SC(0.000100950558f));
    p = fmaf(p, zz, SC(0.00134934322f));
    p = fmaf(p, zz, SC(-0.00367342844f));
    p = fmaf(p, zz, SC(0.00573950773f));
    p = fmaf(p, zz, SC(-0.0076224613f));
    p = fmaf(p, zz, SC(0.00943887047f));
    p = fmaf(p, zz, SC(1.00167406f));
    p = fmaf(p, zz, SC(2.83297682f));
    return p;
}

// packed noise + state update for an element pair.  SUB=false: v = sat(v + n); SUB=true: v = sat(v - n)
template<bool SUB>
__device__ __forceinline__ void upd_pair(uint32_t ba, uint32_t bb, float& va, float& vb,
                                         uint64_t C2, uint64_t Cm1, uint64_t Cm099,
                                         uint64_t Cmln2, uint64_t Cm25,
                                         uint64_t P0, uint64_t P1, uint64_t P2c, uint64_t P3,
                                         uint64_t P4, uint64_t P5, uint64_t P6, uint64_t P7) {
    uint32_t fa = (ba >> 9) | 0x3f800000u;
    uint32_t fb = (bb >> 9) | 0x3f800000u;
    uint64_t F2  = pku(fa, fb);
    uint64_t U2  = add2_(F2, Cm1);          // u  = f - 1     in [0,1), exact
    uint64_t XX2 = fma2_(U2, C2, Cm099);    // x  = 2u - 0.99999994
    uint64_t T2  = fma2_(XX2, XX2, Cm1);    // x^2 - 1  (strictly negative)
    float2 t = unpk(T2);
    float lga = __log2f(fabsf(t.x));
    float lgb = __log2f(fabsf(t.y));
    uint64_t Z2 = fma2_(pkf(lga, lgb), Cmln2, Cm25);   // z = -ln2*lg2 - 2.5 = w - 2.5
    uint64_t P = fma2_(P0, Z2, P1);
    P = fma2_(P, Z2, P2c);
    P = fma2_(P, Z2, P3);
    P = fma2_(P, Z2, P4);
    P = fma2_(P, Z2, P5);
    P = fma2_(P, Z2, P6);
    P = fma2_(P, Z2, P7);
    float2 p  = unpk(P);
    float2 z  = unpk(Z2);
    float2 xx = unpk(XX2);
    if (__builtin_expect(fmaxf(z.x, z.y) >= 2.5f, 0)) {   // rare tail (w >= 5)
        if (z.x >= 2.5f) p.x = tailp(z.x);
        if (z.y >= 2.5f) p.y = tailp(z.y);
    }
    if (SUB) {
        va = __saturatef(fmaf(p.x, -xx.x, va));
        vb = __saturatef(fmaf(p.y, -xx.y, vb));
    } else {
        va = __saturatef(fmaf(p.x,  xx.x, va));
        vb = __saturatef(fmaf(p.y,  xx.y, vb));
    }
}

// scalar noise for the (unused for the target shape) tail path
__device__ float noise_scalar(uint32_t b) {
    float f = __uint_as_float((b >> 9) | 0x3f800000u);
    float u = f - 1.0f;
    float xx = fmaf(u, 2.0f, -0.99999994f);
    float t = fmaf(xx, xx, -1.0f);
    float z = fmaf(__log2f(fabsf(t)), -0.69314718f, -2.5f);
    float p;
    if (z < 2.5f) {
        p = SC(3.43273939e-07f);
        p = fmaf(p, z, SC(-3.5233877e-06f));
        p = fmaf(p, z, SC(-4.39150654e-06f));
        p = fmaf(p, z, SC(0.00021858087f));
        p = fmaf(p, z, SC(-0.00125372503f));
        p = fmaf(p, z, SC(-0.00417768164f));
        p = fmaf(p, z, SC(0.246640727f));
        p = fmaf(p, z, SC(1.50140941f));
    } else {
        p = tailp(z);
    }
    return p * xx;
}

__global__ void __launch_bounds__(256)
diffusion_kernel(const float* __restrict__ x, float* __restrict__ out, int n,
                 uint32_t m13, uint32_t m26, uint32_t m17, uint32_t m16) {
    __shared__ uint4 skeys[N_STEPS + 1];
    for (int i = threadIdx.x; i <= N_STEPS; i += 256)
        skeys[i] = g_keys[i];
    __syncthreads();

    // packed constants (built once; loop-invariant registers)
    const uint64_t C2    = pkf(2.0f, 2.0f);
    const uint64_t Cm1   = pkf(-1.0f, -1.0f);
    const uint64_t Cm099 = pkf(-0.99999994f, -0.99999994f);
    const uint64_t Cmln2 = pkf(-0.69314718f, -0.69314718f);
    const uint64_t Cm25  = pkf(-2.5f, -2.5f);
    const uint64_t P0 = pkf(SC(3.43273939e-07f), SC(3.43273939e-07f));
    const uint64_t P1 = pkf(SC(-3.5233877e-06f), SC(-3.5233877e-06f));
    const uint64_t P2 = pkf(SC(-4.39150654e-06f), SC(-4.39150654e-06f));
    const uint64_t P3 = pkf(SC(0.00021858087f), SC(0.00021858087f));
    const uint64_t P4 = pkf(SC(-0.00125372503f), SC(-0.00125372503f));
    const uint64_t P5 = pkf(SC(-0.00417768164f), SC(-0.00417768164f));
    const uint64_t P6 = pkf(SC(0.246640727f), SC(0.246640727f));
    const uint64_t P7 = pkf(SC(1.50140941f), SC(1.50140941f));

    unsigned tid  = blockIdx.x * 256u + threadIdx.x;
    unsigned base = tid * 4u;
    if (base >= (unsigned)n) return;

    if (base + 4u <= (unsigned)n) {
        float4 v4 = *reinterpret_cast<const float4*>(x + base);
        float v0 = v4.x, v1 = v4.y, v2 = v4.z, v3 = v4.w;
        const uint32_t c0 = base, c1 = base + 1u, c2 = base + 2u, c3 = base + 3u;

        #pragma unroll 2
        for (int t = 0; t < N_STEPS; ++t) {
            uint4 k = skeys[t];
            uint32_t b0 = tf_xor(k.x, k.y, k.z, c0, m13, m26, m17, m16);
            uint32_t b1 = tf_xor(k.x, k.y, k.z, c1, m13, m26, m17, m16);
            uint32_t b2 = tf_xor(k.x, k.y, k.z, c2, m13, m26, m17, m16);
            uint32_t b3 = tf_xor(k.x, k.y, k.z, c3, m13, m26, m17, m16);
            upd_pair<false>(b0, b1, v0, v1, C2, Cm1, Cm099, Cmln2, Cm25, P0,P1,P2,P3,P4,P5,P6,P7);
            upd_pair<false>(b2, b3, v2, v3, C2, Cm1, Cm099, Cmln2, Cm25, P0,P1,P2,P3,P4,P5,P6,P7);
        }
        {   // reverse diffusion: single denoise step
            uint4 k = skeys[N_STEPS];
            uint32_t b0 = tf_xor(k.x, k.y, k.z, c0, m13, m26, m17, m16);
            uint32_t b1 = tf_xor(k.x, k.y, k.z, c1, m13, m26, m17, m16);
            uint32_t b2 = tf_xor(k.x, k.y, k.z, c2, m13, m26, m17, m16);
            uint32_t b3 = tf_xor(k.x, k.y, k.z, c3, m13, m26, m17, m16);
            upd_pair<true>(b0, b1, v0, v1, C2, Cm1, Cm099, Cmln2, Cm25, P0,P1,P2,P3,P4,P5,P6,P7);
            upd_pair<true>(b2, b3, v2, v3, C2, Cm1, Cm099, Cmln2, Cm25, P0,P1,P2,P3,P4,P5,P6,P7);
        }
        *reinterpret_cast<float4*>(out + base) = make_float4(v0, v1, v2, v3);
    } else {
        // scalar tail (not hit for the 25165824-element shape)
        for (unsigned e = base; e < (unsigned)n; ++e) {
            float vv = x[e];
            for (int t = 0; t < N_STEPS; ++t) {
                uint4 k = skeys[t];
                vv = __saturatef(vv + noise_scalar(tf_xor(k.x, k.y, k.z, e, m13, m26, m17, m16)));
            }
            uint4 k = skeys[N_STEPS];
            out[e] = __saturatef(vv - noise_scalar(tf_xor(k.x, k.y, k.z, e, m13, m26, m17, m16)));
        }
    }
}

extern "C" void kernel_launch(void* const* d_in, const int* in_sizes, int n_in,
                              void* d_out, int out_size) {
    const float* x = (const float*)d_in[0];
    float* out     = (float*)d_out;
    int n = out_size;

    prep_keys_kernel<<<1, 1024>>>();

    unsigned threads = (unsigned)((n + 3) / 4);
    unsigned blocks  = (threads + 255u) / 256u;
    // rotation multipliers passed as runtime args so ptxas keeps mul.wide (IMAD.WIDE, fma pipe)
    diffusion_kernel<<<blocks, 256>>>(x, out, n, 1u << 13, 1u << 26, 1u << 17, 1u << 16);
}